// round 4
// baseline (speedup 1.0000x reference)
#include <cuda_runtime.h>

typedef unsigned long long ull;

#define THREADS 256
#define SEQ 512
#define DIN 120
#define NJ 25
#define NC 5
#define ROUTINGS 4
#define TILE_ROWS 64
#define NTILES 8
#define XPAD 121
#define WROW 28

// shared memory layout (in floats)
#define SM_W    0
#define SM_X    (SM_W + DIN*WROW)            // 3360
#define SM_U    (SM_X + TILE_ROWS*XPAD)      // 11104
#define SM_RED  (SM_U + SEQ*NJ)              // 23904
#define SM_SFIN (SM_RED + 8*26)              // 24112
#define SM_TOTF (SM_SFIN + 32)               // 24144 floats = 96576 bytes

__device__ __forceinline__ ull ffma2(ull a, ull b, ull c) {
    ull d;
    asm("fma.rn.f32x2 %0, %1, %2, %3;" : "=l"(d) : "l"(a), "l"(b), "l"(c));
    return d;
}
__device__ __forceinline__ ull pack2(float lo, float hi) {
    ull r; asm("mov.b64 %0, {%1, %2};" : "=l"(r) : "f"(lo), "f"(hi)); return r;
}
__device__ __forceinline__ void unpack2(ull v, float& lo, float& hi) {
    asm("mov.b64 {%0, %1}, %2;" : "=f"(lo), "=f"(hi) : "l"(v));
}

__global__ __launch_bounds__(THREADS, 2)
void caps_kernel(const float* __restrict__ x, const float* __restrict__ W,
                 float* __restrict__ out)
{
    extern __shared__ float sm[];
    float* Ws   = sm + SM_W;
    float* xs   = sm + SM_X;
    float* us   = sm + SM_U;
    float* red  = sm + SM_RED;
    float* sfin = sm + SM_SFIN;

    const int tid = threadIdx.x;
    const int bb  = blockIdx.x;
    const float* xb = x + (size_t)bb * (SEQ * DIN);

    // ---- load W into padded smem rows (k-major, 28 floats/row, zero pad) ----
    for (int idx = tid; idx < DIN * WROW; idx += THREADS) {
        int k = idx / WROW;
        int j = idx - k * WROW;
        Ws[idx] = (j < NJ) ? W[k * NJ + j] : 0.0f;
    }

    const int s    = tid & 3;        // k-quarter: covers k in [30s, 30s+30)
    const int rloc = tid >> 2;       // local row within tile (0..63)
    const float* xrow0 = xs + rloc * XPAD + s * 30;

    // ================= GEMM: u_hat[512][25] = x[512][120] @ W[120][25] =================
    for (int T = 0; T < NTILES; ++T) {
        __syncthreads();   // xs reuse guard (also covers W-load completion at T=0)

        // coalesced tile load: 64 rows x 120 cols
        const float4* xg4 = (const float4*)(xb + T * (TILE_ROWS * DIN));
        #pragma unroll
        for (int m = 0; m < 8; ++m) {
            int idx4 = tid + THREADS * m;
            if (idx4 < TILE_ROWS * DIN / 4) {
                float4 v = xg4[idx4];
                int r = idx4 / 30;
                int c = (idx4 - r * 30) * 4;
                float* p = xs + r * XPAD + c;
                p[0] = v.x; p[1] = v.y; p[2] = v.z; p[3] = v.w;
            }
        }
        __syncthreads();

        // 13 packed f32x2 accumulators = 26 output cols (25 used)
        ull acc[13];
        #pragma unroll
        for (int t = 0; t < 13; ++t) acc[t] = 0ull;

        #pragma unroll 6
        for (int kk = 0; kk < 30; ++kk) {
            int k = s * 30 + kk;
            float xv = xrow0[kk];
            ull x2 = pack2(xv, xv);
            const double2* wr = (const double2*)(Ws + k * WROW);  // 16B aligned
            #pragma unroll
            for (int t = 0; t < 7; ++t) {
                double2 w = wr[t];                       // LDS.128, broadcast
                acc[2 * t] = ffma2(x2, __double_as_longlong(w.x), acc[2 * t]);
                if (t < 6)
                    acc[2 * t + 1] = ffma2(x2, __double_as_longlong(w.y), acc[2 * t + 1]);
            }
        }

        float uv[26];
        #pragma unroll
        for (int t = 0; t < 13; ++t) unpack2(acc[t], uv[2 * t], uv[2 * t + 1]);

        // reduce across the 4 k-quarters (lanes 4r..4r+3 in same warp)
        #pragma unroll
        for (int v = 0; v < NJ; ++v) {
            uv[v] += __shfl_xor_sync(0xffffffffu, uv[v], 1);
            uv[v] += __shfl_xor_sync(0xffffffffu, uv[v], 2);
        }
        int grow = T * TILE_ROWS + rloc;
        int c0 = s * 7;
        int c1 = (s == 3) ? NJ : (c0 + 7);
        for (int c = c0; c < c1; ++c) us[grow * NJ + c] = uv[c];
    }
    __syncthreads();

    // ================= dynamic routing (4 iterations) =================
    // thread owns inp rows j0 = tid, j1 = tid + 256
    float ua[NJ], ub[NJ];
    const int j0 = tid, j1 = tid + THREADS;
    #pragma unroll
    for (int v = 0; v < NJ; ++v) { ua[v] = us[j0 * NJ + v]; ub[v] = us[j1 * NJ + v]; }

    float l0[NC] = {0, 0, 0, 0, 0};   // routing logits b[i][j0]
    float l1[NC] = {0, 0, 0, 0, 0};   // routing logits b[i][j1]
    const int wid  = tid >> 5;
    const int lane = tid & 31;

    for (int it = 0; it < ROUTINGS; ++it) {
        // softmax over the capsule axis (5)
        float c0[NC], c1[NC];
        {
            float m0 = l0[0], m1 = l1[0];
            #pragma unroll
            for (int i = 1; i < NC; ++i) { m0 = fmaxf(m0, l0[i]); m1 = fmaxf(m1, l1[i]); }
            float s0 = 0.f, s1 = 0.f;
            #pragma unroll
            for (int i = 0; i < NC; ++i) {
                c0[i] = __expf(l0[i] - m0); s0 += c0[i];
                c1[i] = __expf(l1[i] - m1); s1 += c1[i];
            }
            float r0 = __fdividef(1.f, s0), r1 = __fdividef(1.f, s1);
            #pragma unroll
            for (int i = 0; i < NC; ++i) { c0[i] *= r0; c1[i] *= r1; }
        }

        // partial s[i][k] = sum_j c[i][j] * u[i][j][k]
        float part[NJ];
        #pragma unroll
        for (int i = 0; i < NC; ++i)
            #pragma unroll
            for (int k = 0; k < NC; ++k)
                part[i * NC + k] = c0[i] * ua[i * NC + k] + c1[i] * ub[i * NC + k];

        // block reduce 25 values over 256 threads
        #pragma unroll
        for (int v = 0; v < NJ; ++v) {
            part[v] += __shfl_xor_sync(0xffffffffu, part[v], 16);
            part[v] += __shfl_xor_sync(0xffffffffu, part[v], 8);
            part[v] += __shfl_xor_sync(0xffffffffu, part[v], 4);
            part[v] += __shfl_xor_sync(0xffffffffu, part[v], 2);
            part[v] += __shfl_xor_sync(0xffffffffu, part[v], 1);
        }
        if (lane == 0) {
            #pragma unroll
            for (int v = 0; v < NJ; ++v) red[wid * 26 + v] = part[v];
        }
        __syncthreads();
        if (tid < NJ) {
            float a = 0.f;
            #pragma unroll
            for (int w = 0; w < 8; ++w) a += red[w * 26 + tid];
            sfin[tid] = a;
        }
        __syncthreads();

        // everyone reads the reduced s, computes squash scale (redundant, deterministic)
        float sv[NJ];
        #pragma unroll
        for (int v = 0; v < NJ; ++v) sv[v] = sfin[v];
        float inv[NC];
        #pragma unroll
        for (int i = 0; i < NC; ++i) {
            float n2 = 1e-7f;
            #pragma unroll
            for (int k = 0; k < NC; ++k) n2 += sv[i * NC + k] * sv[i * NC + k];
            inv[i] = rsqrtf(n2);
        }

        if (it < ROUTINGS - 1) {
            // b[i][j] = sum_k outputs[i][k] * u[i][j][k]   (replace, per reference)
            #pragma unroll
            for (int i = 0; i < NC; ++i) {
                float d0 = 0.f, d1 = 0.f;
                #pragma unroll
                for (int k = 0; k < NC; ++k) {
                    float o = sv[i * NC + k] * inv[i];
                    d0 += o * ua[i * NC + k];
                    d1 += o * ub[i * NC + k];
                }
                l0[i] = d0; l1[i] = d1;
            }
        } else {
            if (tid < NJ) out[bb * NJ + tid] = sv[tid] * inv[tid / NC];
        }
    }
}

extern "C" void kernel_launch(void* const* d_in, const int* in_sizes, int n_in,
                              void* d_out, int out_size) {
    const float* x = (const float*)d_in[0];
    const float* W = (const float*)d_in[1];
    float* out = (float*)d_out;
    int batch = in_sizes[0] / (SEQ * DIN);

    cudaFuncSetAttribute(caps_kernel, cudaFuncAttributeMaxDynamicSharedMemorySize,
                         SM_TOTF * (int)sizeof(float));
    caps_kernel<<<batch, THREADS, SM_TOTF * (int)sizeof(float)>>>(x, W, out);
}

// round 5
// speedup vs baseline: 2.2694x; 2.2694x over previous
#include <cuda_runtime.h>

typedef unsigned long long ull;

#define THREADS 256
#define SEQ 512
#define DIN 120
#define NJ 25
#define NC 5
#define ROUTINGS 4
#define WROW 28   // padded W row (floats) -> 7 x 16B, keeps LDS.128 alignment

__device__ __forceinline__ ull ffma2(ull a, ull b, ull c) {
    ull d;
    asm("fma.rn.f32x2 %0, %1, %2, %3;" : "=l"(d) : "l"(a), "l"(b), "l"(c));
    return d;
}
__device__ __forceinline__ ull pack2(float lo, float hi) {
    ull r; asm("mov.b64 %0, {%1, %2};" : "=l"(r) : "f"(lo), "f"(hi)); return r;
}
__device__ __forceinline__ void unpack2(ull v, float& lo, float& hi) {
    asm("mov.b64 {%0, %1}, %2;" : "=f"(lo), "=f"(hi) : "l"(v));
}

__global__ __launch_bounds__(THREADS, 3)
void caps_kernel(const float* __restrict__ x, const float* __restrict__ W,
                 float* __restrict__ out)
{
    __shared__ float Ws[DIN * WROW];     // 13.4 KB, broadcast operand
    __shared__ float red[8 * 26];        // per-warp partials
    __shared__ float sfin[32];           // reduced s[25]

    const int tid = threadIdx.x;
    const int bb  = blockIdx.x;
    const float* xb = x + (size_t)bb * (SEQ * DIN);

    // ---- stage W into padded smem rows (k-major, 28 floats/row, zero pad) ----
    for (int idx = tid; idx < DIN * WROW; idx += THREADS) {
        int k = idx / WROW;
        int j = idx - k * WROW;
        Ws[idx] = (j < NJ) ? W[k * NJ + j] : 0.0f;
    }
    __syncthreads();

    // ================ GEMM: this thread computes full rows j0, j1 ================
    const int j0 = tid, j1 = tid + THREADS;
    const float4* pa = (const float4*)(xb + j0 * DIN);   // 30 float4 per row
    const float4* pb = (const float4*)(xb + j1 * DIN);

    ull acc0[13], acc1[13];
    #pragma unroll
    for (int t = 0; t < 13; ++t) { acc0[t] = 0ull; acc1[t] = 0ull; }

    #pragma unroll 6
    for (int kc = 0; kc < 30; ++kc) {
        float4 va = pa[kc];          // own-row stream, L1 line reused 8x
        float4 vb = pb[kc];
        #pragma unroll
        for (int q = 0; q < 4; ++q) {
            float av = (&va.x)[q];
            float bv = (&vb.x)[q];
            ull a2 = pack2(av, av);
            ull b2 = pack2(bv, bv);
            const double2* wr = (const double2*)(Ws + (kc * 4 + q) * WROW);
            #pragma unroll
            for (int t = 0; t < 7; ++t) {
                double2 w = wr[t];                      // uniform-address LDS.128
                ull wlo = __double_as_longlong(w.x);
                acc0[2 * t] = ffma2(a2, wlo, acc0[2 * t]);
                acc1[2 * t] = ffma2(b2, wlo, acc1[2 * t]);
                if (t < 6) {
                    ull whi = __double_as_longlong(w.y);
                    acc0[2 * t + 1] = ffma2(a2, whi, acc0[2 * t + 1]);
                    acc1[2 * t + 1] = ffma2(b2, whi, acc1[2 * t + 1]);
                }
            }
        }
    }

    // accumulators become the routing-resident u_hat rows
    float ua[26], ub[26];
    #pragma unroll
    for (int t = 0; t < 13; ++t) {
        unpack2(acc0[t], ua[2 * t], ua[2 * t + 1]);
        unpack2(acc1[t], ub[2 * t], ub[2 * t + 1]);
    }

    // ================= dynamic routing (4 iterations) =================
    float l0[NC] = {0, 0, 0, 0, 0};
    float l1[NC] = {0, 0, 0, 0, 0};
    const int wid  = tid >> 5;
    const int lane = tid & 31;

    for (int it = 0; it < ROUTINGS; ++it) {
        // softmax over the capsule axis (5)
        float c0[NC], c1[NC];
        {
            float m0 = l0[0], m1 = l1[0];
            #pragma unroll
            for (int i = 1; i < NC; ++i) { m0 = fmaxf(m0, l0[i]); m1 = fmaxf(m1, l1[i]); }
            float s0 = 0.f, s1 = 0.f;
            #pragma unroll
            for (int i = 0; i < NC; ++i) {
                c0[i] = __expf(l0[i] - m0); s0 += c0[i];
                c1[i] = __expf(l1[i] - m1); s1 += c1[i];
            }
            float r0 = __fdividef(1.f, s0), r1 = __fdividef(1.f, s1);
            #pragma unroll
            for (int i = 0; i < NC; ++i) { c0[i] *= r0; c1[i] *= r1; }
        }

        // partial s[i][k] over this thread's two rows
        float part[NJ];
        #pragma unroll
        for (int i = 0; i < NC; ++i)
            #pragma unroll
            for (int k = 0; k < NC; ++k)
                part[i * NC + k] = c0[i] * ua[i * NC + k] + c1[i] * ub[i * NC + k];

        // block reduce 25 values over 256 threads
        #pragma unroll
        for (int v = 0; v < NJ; ++v) {
            part[v] += __shfl_xor_sync(0xffffffffu, part[v], 16);
            part[v] += __shfl_xor_sync(0xffffffffu, part[v], 8);
            part[v] += __shfl_xor_sync(0xffffffffu, part[v], 4);
            part[v] += __shfl_xor_sync(0xffffffffu, part[v], 2);
            part[v] += __shfl_xor_sync(0xffffffffu, part[v], 1);
        }
        if (lane == 0) {
            #pragma unroll
            for (int v = 0; v < NJ; ++v) red[wid * 26 + v] = part[v];
        }
        __syncthreads();
        if (tid < NJ) {
            float a = 0.f;
            #pragma unroll
            for (int w = 0; w < 8; ++w) a += red[w * 26 + tid];
            sfin[tid] = a;
        }
        __syncthreads();

        // squash scale per capsule, read s from smem (broadcast, saves regs)
        float inv[NC];
        #pragma unroll
        for (int i = 0; i < NC; ++i) {
            float n2 = 1e-7f;
            #pragma unroll
            for (int k = 0; k < NC; ++k) {
                float sv = sfin[i * NC + k];
                n2 += sv * sv;
            }
            inv[i] = rsqrtf(n2);
        }

        if (it < ROUTINGS - 1) {
            // b[i][j] = sum_k outputs[i][k] * u[i][j][k]   (replace, per reference)
            #pragma unroll
            for (int i = 0; i < NC; ++i) {
                float d0 = 0.f, d1 = 0.f;
                #pragma unroll
                for (int k = 0; k < NC; ++k) {
                    float o = sfin[i * NC + k] * inv[i];
                    d0 += o * ua[i * NC + k];
                    d1 += o * ub[i * NC + k];
                }
                l0[i] = d0; l1[i] = d1;
            }
        } else {
            if (tid < NJ) out[bb * NJ + tid] = sfin[tid] * inv[tid / NC];
        }
    }
}

extern "C" void kernel_launch(void* const* d_in, const int* in_sizes, int n_in,
                              void* d_out, int out_size) {
    const float* x = (const float*)d_in[0];
    const float* W = (const float*)d_in[1];
    float* out = (float*)d_out;
    int batch = in_sizes[0] / (SEQ * DIN);
    caps_kernel<<<batch, THREADS>>>(x, W, out);
}